// round 17
// baseline (speedup 1.0000x reference)
#include <cuda_runtime.h>
#include <cuda_fp16.h>
#include <cstdint>

// ---------------- problem dims ----------------
#define NT 4
#define NB 8
#define NC1 64
#define NC2 128
#define HH 128
#define WW 128
#define HW 16384
#define NIMG 32
#define NSPIKES 33554432       // NIMG*NC1*HW
#define NY 67108864            // NIMG*NC2*HW
#define NELEM_PER_CH 524288
#define NW 73728
#define NTILES 2048            // 32 images x 64 tiles (16x16 px)

// ---------------- conv smem layout ----------------
#define B_BYTES 147456         // 9 taps x 128 oc x 64 ch fp16, resident
#define HALO_BYTES 41472       // 324 rows (18x18) x 128 B
#define SMEM_TOTAL (B_BYTES + 2*HALO_BYTES)   // 230400

// ---------------- device scratch ----------------
__device__ __half g_spikes[NSPIKES];          // [n][y][x][c]  channel-last
__device__ __half g_y[NY];                    // [n][o][y][x]  fp16 intermediate
__device__ __half g_w[9*NC2*NC1];             // [kk][o][c] fp16 weights
__device__ float g_ps[NC2*NTILES];            // per-(ch,tile) sum
__device__ float g_pq[NC2*NTILES];            // per-(ch,tile) sumsq
__device__ float g_scale[NC2];
__device__ float g_shift[NC2];
__device__ int g_probe_sink;

// ---------------- helpers ----------------
__device__ __forceinline__ uint32_t smem_u32(const void* p) {
    uint32_t a;
    asm("{ .reg .u64 t; cvta.to.shared.u64 t, %1; cvt.u32.u64 %0, t; }"
        : "=r"(a) : "l"(p));
    return a;
}

__device__ __forceinline__ void mma_f16(float* d, const uint32_t* a,
                                        const uint32_t* b) {
    asm volatile(
        "mma.sync.aligned.m16n8k16.row.col.f32.f16.f16.f32 "
        "{%0,%1,%2,%3}, {%4,%5,%6,%7}, {%8,%9}, {%0,%1,%2,%3};"
        : "+f"(d[0]), "+f"(d[1]), "+f"(d[2]), "+f"(d[3])
        : "r"(a[0]), "r"(a[1]), "r"(a[2]), "r"(a[3]), "r"(b[0]), "r"(b[1]));
}

// ---------------- probe: no-op launch so ncu's fixed capture slot (#4)
// lands on conv_kernel ----------------
__global__ void probe_kernel() {
    if (threadIdx.x == 0) g_probe_sink = 1;   // constant -> deterministic
}

// ---------------- K1: LIF -> fp16 spikes, channel-last ----------------
// Double-buffered transpose smem: ONE barrier per t-step.
__global__ void lif_kernel(const float* __restrict__ x) {
    __shared__ __half sbuf[2][128][24];   // 48B rows -> 16B-aligned uint4 reads
    const int b = blockIdx.x, y = blockIdx.y, cg = blockIdx.z;
    const int tid = threadIdx.x;
    const int c0 = cg * 16;
    const int wo = tid >> 1;
    const int co = (tid & 1) * 8;
    float mem[8], s[8];
#pragma unroll
    for (int j = 0; j < 8; j++) { mem[j] = 0.f; s[j] = 0.f; }
#pragma unroll
    for (int t = 0; t < NT; t++) {
        size_t xb = ((((size_t)t * NB + b) * NC1 + c0) * HH + y) * WW;
#pragma unroll
        for (int j = 0; j < 8; j++) {
            int idx = j * 256 + tid;
            int cl = idx >> 7, w = idx & 127;
            float xv = __ldcs(&x[xb + (size_t)cl * HW + w]);   // streaming
            mem[j] = (mem[j] - 0.5f * s[j]) * 0.25f + xv;
            s[j] = rintf(fminf(fmaxf(mem[j], 0.f), 1.f));
            sbuf[t & 1][w][cl] = __float2half_rn(s[j]);   // {0,1} exact
        }
        __syncthreads();   // writes(t) done; also orders reads(t-2) before reuse
        uint4 v = *(const uint4*)&sbuf[t & 1][wo][co];
        size_t ob = (((size_t)(t * NB + b) * HH + y) * WW + wo) * NC1 + c0 + co;
        *(uint4*)(&g_spikes[ob]) = v;
    }
}

// ---------------- K0: weights -> fp16, [kk][o][c] ----------------
__global__ void wprep_kernel(const float* __restrict__ w) {
    int i = blockIdx.x * 256 + threadIdx.x;
    if (i < NW) {
        int kx = i % 3, ky = (i / 3) % 3, c = (i / 9) % NC1, o = i / (NC1 * 9);
        g_w[((ky * 3 + kx) * NC2 + o) * NC1 + c] = __float2half_rn(w[i]);
    }
}

// ---------------- K2: persistent halo implicit-GEMM conv + fused stats ----
// grid = #SMs, 512 threads = 16 warps (4 px x 4 oc). Tile: 256 px x 128 oc.
// B (all 9 taps) resident in smem; per tile a single 18x18x64 halo load feeds
// all 36 MMA k-steps via per-lane-addressed ldmatrix (no per-tap barriers).
// B fragments fetched as x4 (both nn of a pair per instr).
__global__ void __launch_bounds__(512, 1) conv_kernel(int nsm) {
    extern __shared__ unsigned char smem[];
    const uint32_t sb = smem_u32(smem);
    const int tid = threadIdx.x;
    const int l = tid & 31, wid = tid >> 5;
    const int wm = wid & 3, wn = wid >> 2;

    // ---- A-side per-lane constants ----
    const int kcA = l >> 4;
    const int xl = ((l & 7) << 1) | ((l >> 3) & 1);   // permuted x of this lane's rows
    const int hm0 = (wm * 4) * 18 + xl;               // + m*18 + dk -> halo row
    // ---- B-side per-lane constants (x4 ldmatrix: lanes 16-31 -> +8 oc rows) ----
    const int rB4 = wn * 32 + (l & 7) + ((l >> 4) & 1) * 8;  // + pp*16
    const int kc4 = (l >> 3) & 1;
    const int l7 = l & 7;

    // ---- load resident B: 1152 rows x 128 B, swizzled by row&7 ----
#pragma unroll
    for (int j = 0; j < 18; j++) {
        int cid = tid + j * 512;          // 9216 chunks of 16 B
        int r = cid >> 3, cc = cid & 7;
        unsigned long long src = (unsigned long long)__cvta_generic_to_global(
            (void*)(g_w + (size_t)r * 64 + cc * 8));
        uint32_t dst = sb + (uint32_t)r * 128 + ((cc ^ (r & 7)) << 4);
        asm volatile("cp.async.cg.shared.global [%0], [%1], 16, 16;"
                     :: "r"(dst), "l"(src) : "memory");
    }

    auto issue_halo = [&](int t, int q) {
        const int n = t >> 6;
        const int gy0 = ((t >> 3) & 7) * 16 - 1;
        const int gx0 = (t & 7) * 16 - 1;
        const uint32_t hb = sb + B_BYTES + (uint32_t)q * HALO_BYTES;
#pragma unroll
        for (int j = 0; j < 6; j++) {
            int cid = tid + j * 512;      // 2592 chunks of 16 B
            if (cid < 2592) {
                int hr = cid >> 3, cc = cid & 7;
                int hy = hr / 18;
                int hx = hr - hy * 18;
                int gy = gy0 + hy, gx = gx0 + hx;
                bool ok = ((unsigned)gy < HH) && ((unsigned)gx < WW);
                int cgy = ok ? gy : 0, cgx = ok ? gx : 0;
                unsigned long long src =
                    (unsigned long long)__cvta_generic_to_global(
                        (void*)(g_spikes +
                                (((size_t)n * HH + cgy) * WW + cgx) * NC1 + cc * 8));
                uint32_t dst = hb + (uint32_t)hr * 128 +
                               ((cc ^ ((hr >> 1) & 7)) << 4);
                int sz = ok ? 16 : 0;
                asm volatile("cp.async.cg.shared.global [%0], [%1], 16, %2;"
                             :: "r"(dst), "l"(src), "r"(sz) : "memory");
            }
        }
        asm volatile("cp.async.commit_group;" ::: "memory");
    };

    int tile = blockIdx.x;
    issue_halo(tile, 0);   // commits B + halo0 as group 0
    int it = 0;
    float acc[4][4][4];

    while (tile < NTILES) {
        asm volatile("cp.async.wait_group 0;" ::: "memory");
        __syncthreads();                               // barrier 1: halo ready
        const int nxt = tile + nsm;
        if (nxt < NTILES) issue_halo(nxt, (it + 1) & 1);
        const uint32_t hs = sb + B_BYTES + (uint32_t)(it & 1) * HALO_BYTES;

#pragma unroll
        for (int m = 0; m < 4; m++)
#pragma unroll
            for (int nn = 0; nn < 4; nn++)
#pragma unroll
                for (int e = 0; e < 4; e++) acc[m][nn][e] = 0.f;

        // ---- 9 taps x 4 k-steps, no barriers, no waits ----
#pragma unroll 1
        for (int dy = 0; dy < 3; dy++) {
#pragma unroll
            for (int dx = 0; dx < 3; dx++) {
                const int dk = dy * 18 + dx;
                const uint32_t bB = sb + (uint32_t)(dy * 3 + dx) * 16384;
#pragma unroll
                for (int ks = 0; ks < 4; ks++) {
                    uint32_t bf[4][2];
#pragma unroll
                    for (int pp = 0; pp < 2; pp++) {
                        uint32_t off = (uint32_t)(rB4 + pp * 16) * 128 +
                                       (((ks * 2 + kc4) ^ l7) << 4);
                        asm volatile(
                            "ldmatrix.sync.aligned.m8n8.x4.shared.b16 "
                            "{%0,%1,%2,%3}, [%4];"
                            : "=r"(bf[pp * 2][0]), "=r"(bf[pp * 2][1]),
                              "=r"(bf[pp * 2 + 1][0]), "=r"(bf[pp * 2 + 1][1])
                            : "r"(bB + off));
                    }
#pragma unroll
                    for (int m = 0; m < 4; m++) {
                        const int hr = hm0 + m * 18 + dk;
                        uint32_t ad = hs + (uint32_t)hr * 128 +
                                      (((ks * 2 + kcA) ^ ((hr >> 1) & 7)) << 4);
                        uint32_t a[4];
                        asm volatile(
                            "ldmatrix.sync.aligned.m8n8.x4.shared.b16 "
                            "{%0,%1,%2,%3}, [%4];"
                            : "=r"(a[0]), "=r"(a[1]), "=r"(a[2]), "=r"(a[3])
                            : "r"(ad));
#pragma unroll
                        for (int nn = 0; nn < 4; nn++)
                            mma_f16(acc[m][nn], a, bf[nn]);
                    }
                }
            }
        }

        // ---- epilogue 1: packed fp16 y stores ----
        const int n = tile >> 6;
        const int ty0 = ((tile >> 3) & 7) * 16, tx0 = (tile & 7) * 16;
#pragma unroll
        for (int m = 0; m < 4; m++) {
            const int y = ty0 + wm * 4 + m;
            const int x = tx0 + ((l >> 2) << 1);
#pragma unroll
            for (int nn = 0; nn < 4; nn++) {
                const int oc = wn * 32 + nn * 8 + (l & 3) * 2;
                __half* p = g_y + ((size_t)n * NC2 + oc) * HW + y * WW + x;
                *(__half2*)p = __floats2half2_rn(acc[m][nn][0], acc[m][nn][2]);
                *(__half2*)(p + HW) = __floats2half2_rn(acc[m][nn][1], acc[m][nn][3]);
            }
        }

        __syncthreads();   // barrier 2: MMA reads of this halo stage done
        // ---- epilogue 2: fused BN partial stats (sred aliases dead stage) ----
        float* sred = (float*)(smem + B_BYTES + (size_t)(it & 1) * HALO_BYTES);
#pragma unroll
        for (int nn = 0; nn < 4; nn++) {
            float s0 = 0.f, s1 = 0.f, q0 = 0.f, q1 = 0.f;
#pragma unroll
            for (int m = 0; m < 4; m++) {
                float v0 = acc[m][nn][0], v1 = acc[m][nn][1];
                float v2 = acc[m][nn][2], v3 = acc[m][nn][3];
                s0 += v0 + v2; q0 += v0 * v0 + v2 * v2;
                s1 += v1 + v3; q1 += v1 * v1 + v3 * v3;
            }
#pragma unroll
            for (int o = 4; o <= 16; o <<= 1) {
                s0 += __shfl_xor_sync(0xffffffffu, s0, o);
                s1 += __shfl_xor_sync(0xffffffffu, s1, o);
                q0 += __shfl_xor_sync(0xffffffffu, q0, o);
                q1 += __shfl_xor_sync(0xffffffffu, q1, o);
            }
            if (l < 4) {
                float* p = sred + ((wid * 4 + nn) * 4 + l) * 4;
                p[0] = s0; p[1] = s1; p[2] = q0; p[3] = q1;
            }
        }
        __syncthreads();   // barrier 3
        if (tid < NC2) {
            const int c = tid;
            const int cwn = c >> 5, cnn = (c >> 3) & 3, csel = (c >> 1) & 3,
                      ccol = c & 1;
            float S = 0.f, Q = 0.f;
#pragma unroll
            for (int wm2 = 0; wm2 < 4; wm2++) {
                const float* p = sred + (((cwn * 4 + wm2) * 4 + cnn) * 4 + csel) * 4;
                S += p[ccol];
                Q += p[2 + ccol];
            }
            g_ps[c * NTILES + tile] = S;
            g_pq[c * NTILES + tile] = Q;
        }
        tile = nxt;
        it++;
    }
}

// ---------------- K3: finalize BN scale/shift ----------------
__global__ void stats_final(const float* __restrict__ gamma,
                            const float* __restrict__ beta) {
    const int c = blockIdx.x;
    const int tid = threadIdx.x;
    float s = 0.f, q = 0.f;
    for (int i = tid; i < NTILES; i += 1024) {
        s += g_ps[c * NTILES + i];
        q += g_pq[c * NTILES + i];
    }
    __shared__ float rs[1024], rq[1024];
    rs[tid] = s; rq[tid] = q;
    __syncthreads();
    for (int st = 512; st > 0; st >>= 1) {
        if (tid < st) { rs[tid] += rs[tid + st]; rq[tid] += rq[tid + st]; }
        __syncthreads();
    }
    if (tid == 0) {
        const float inv = 1.f / (float)NELEM_PER_CH;
        float mean = rs[0] * inv;
        float var = fmaxf(rq[0] * inv - mean * mean, 0.f);
        float r = rsqrtf(var + 1e-5f);
        float sc = gamma[c] * r;
        g_scale[c] = sc;
        g_shift[c] = beta[c] - mean * sc;
    }
}

// ---------------- K4: apply BN (fp16 in, fp32 out), reverse + streaming ----
__global__ void bn_apply(float* __restrict__ out) {
    const size_t bi = (size_t)(gridDim.x - 1 - blockIdx.x);   // newest y first
    size_t i = bi * 256 + threadIdx.x;   // uint4 index (8 halves)
    const uint4 v = __ldcs((const uint4*)g_y + i);
    int c = (int)((i >> 11) & 127);
    float sc = g_scale[c], sh = g_shift[c];
    float2 f0 = __half22float2(*(const __half2*)&v.x);
    float2 f1 = __half22float2(*(const __half2*)&v.y);
    float2 f2 = __half22float2(*(const __half2*)&v.z);
    float2 f3 = __half22float2(*(const __half2*)&v.w);
    float4 o0, o1;
    o0.x = fmaf(f0.x, sc, sh); o0.y = fmaf(f0.y, sc, sh);
    o0.z = fmaf(f1.x, sc, sh); o0.w = fmaf(f1.y, sc, sh);
    o1.x = fmaf(f2.x, sc, sh); o1.y = fmaf(f2.y, sc, sh);
    o1.z = fmaf(f3.x, sc, sh); o1.w = fmaf(f3.y, sc, sh);
    __stcs((float4*)out + i * 2, o0);        // evict-first: protect y in L2
    __stcs((float4*)out + i * 2 + 1, o1);
}

extern "C" void kernel_launch(void* const* d_in, const int* in_sizes, int n_in,
                              void* d_out, int out_size) {
    const float* x     = (const float*)d_in[0];
    const float* w     = (const float*)d_in[1];
    const float* gamma = (const float*)d_in[2];
    const float* beta  = (const float*)d_in[3];
    float* out = (float*)d_out;

    static int nsm = 0;
    if (nsm == 0) {
        int dev = 0;
        cudaGetDevice(&dev);
        if (cudaDeviceGetAttribute(&nsm, cudaDevAttrMultiProcessorCount, dev)
                != cudaSuccess || nsm <= 0)
            nsm = 148;
    }

    cudaFuncSetAttribute(conv_kernel, cudaFuncAttributeMaxDynamicSharedMemorySize,
                         SMEM_TOTAL);

    wprep_kernel<<<(NW + 255) / 256, 256>>>(w);     // launch 1
    lif_kernel<<<dim3(NB, HH, 4), 256>>>(x);        // launch 2
    probe_kernel<<<1, 32>>>();                      // launch 3 (aligns ncu slot)
    conv_kernel<<<nsm, 512, SMEM_TOTAL>>>(nsm);     // launch 4  <- profiled
    stats_final<<<NC2, 1024>>>(gamma, beta);
    bn_apply<<<NY / 8 / 256, 256>>>(out);
}